// round 1
// baseline (speedup 1.0000x reference)
#include <cuda_runtime.h>
#include <math.h>
#include <float.h>

#define Bz   8
#define Lc   3
#define Tt   3
#define ENT  50000
#define NTR  1000000
#define RR   200
#define NRELS 401
#define HH   256
#define TAUF 10.0f
#define TOPKN 1000

// ---------------- device scratch (static; no allocation allowed) ----------------
__device__ float    g_W[Tt*Bz*Lc*NRELS];       // softmax'd relation weights per hop
__device__ float    g_hseq[Lc*2*Bz*4*HH];      // LSTM hidden states [l][dir][b][step][H]
__device__ float    g_scur[Bz*Lc*ENT];         // normalized state
__device__ float    g_snext[Bz*Lc*ENT];        // propagate accumulator
__device__ float    g_th[Bz*Lc];               // per-slice top-k threshold
__device__ int      g_offf[ENT+1];             // CSR by head (forward messages)
__device__ int      g_offb[ENT+1];             // CSR by tail2 (backward messages)
__device__ int      g_curf[ENT];
__device__ int      g_curb[ENT];
__device__ unsigned g_payf[NTR];               // packed (tail | rel<<16)
__device__ unsigned g_payb[NTR];               // packed (head | rel<<16)

__device__ __forceinline__ float sigmoidf(float x){ return 1.0f/(1.0f+expf(-x)); }

// ---------------- 1) LSTMs: one block per (l, dir, b); 1024 threads = gates ----------------
__global__ void lstm_kernel(const int* __restrict__ input_r, const float* __restrict__ emb,
    const float* __restrict__ Wih_f, const float* __restrict__ Whh_f,
    const float* __restrict__ bih_f, const float* __restrict__ bhh_f,
    const float* __restrict__ Wih_b, const float* __restrict__ Whh_b,
    const float* __restrict__ bih_b, const float* __restrict__ bhh_b)
{
    int blk = blockIdx.x;          // 48 blocks
    int b   = blk & 7;
    int dl  = blk >> 3;
    int dir = dl & 1;              // 0 = forward, 1 = backward (runs reversed seq)
    int l   = dl >> 1;
    const float* Wih = dir ? Wih_b : Wih_f;
    const float* Whh = dir ? Whh_b : Whh_f;
    const float* bih = dir ? bih_b : bih_f;
    const float* bhh = dir ? bhh_b : bhh_f;

    __shared__ __align__(16) float xq[HH];     // query relation embedding
    __shared__ __align__(16) float xl[HH];     // emb[last]
    __shared__ __align__(16) float hsm[HH];
    __shared__ float gates[4*HH];

    int tid = threadIdx.x;
    if (tid < HH){
        int r = input_r[b];
        xq[tid]  = emb[r*HH + tid];
        xl[tid]  = emb[(NRELS-1)*HH + tid];
        hsm[tid] = 0.0f;
    }
    __syncthreads();

    int g = tid;  // gate index 0..1023
    const float4* wi = (const float4*)(Wih + ((size_t)l*4*HH + g)*HH);
    const float4* wh = (const float4*)(Whh + ((size_t)l*4*HH + g)*HH);
    float bb = bih[l*4*HH + g] + bhh[l*4*HH + g];
    float pq = bb, pl = bb;       // input projections for the two distinct inputs
    const float4* x4q = (const float4*)xq;
    const float4* x4l = (const float4*)xl;
    #pragma unroll 8
    for (int k = 0; k < HH/4; k++){
        float4 w = wi[k]; float4 a = x4q[k]; float4 c = x4l[k];
        pq += w.x*a.x + w.y*a.y + w.z*a.z + w.w*a.w;
        pl += w.x*c.x + w.y*c.y + w.z*c.z + w.w*c.w;
    }

    float cst = 0.0f;  // cell state, owned by tid<256
    float* hout = g_hseq + ((size_t)((l*2+dir)*Bz + b))*4*HH;
    const float4* h4 = (const float4*)hsm;

    for (int step = 0; step < 4; step++){
        // forward seq: [q,q,q,last]; backward (reversed) seq: [last,q,q,q]
        bool useLast = (dir == 0) ? (step == 3) : (step == 0);
        float acc = useLast ? pl : pq;
        #pragma unroll 8
        for (int k = 0; k < HH/4; k++){
            float4 w = wh[k]; float4 h = h4[k];
            acc += w.x*h.x + w.y*h.y + w.z*h.z + w.w*h.w;
        }
        gates[g] = acc;
        __syncthreads();
        if (tid < HH){
            float i_ = sigmoidf(gates[tid]);
            float f_ = sigmoidf(gates[HH + tid]);
            float gg = tanhf(gates[2*HH + tid]);
            float o_ = sigmoidf(gates[3*HH + tid]);
            cst = f_*cst + i_*gg;
            float h = o_*tanhf(cst);
            hsm[tid] = h;
            hout[step*HH + tid] = h;
        }
        __syncthreads();
    }
}

// ---------------- 2) logits + softmax -> g_W ----------------
__global__ void wsoft_kernel(const float* __restrict__ linW, const float* __restrict__ linb)
{
    int blk = blockIdx.x;              // b*9 + t*3 + l  (72 blocks, 512 threads)
    int l = blk % Lc;
    int t = (blk / Lc) % Tt;
    int b = blk / (Lc*Tt);
    __shared__ __align__(16) float hcat[2*HH];
    __shared__ float red[512];
    int tid = threadIdx.x;
    if (tid < HH)
        hcat[tid] = g_hseq[((size_t)((l*2+0)*Bz + b))*4*HH + t*HH + tid];
    else
        hcat[tid] = g_hseq[((size_t)((l*2+1)*Bz + b))*4*HH + (3-t)*HH + (tid-HH)];
    __syncthreads();

    float logit = 0.0f;
    float v = -FLT_MAX;
    if (tid < NRELS){
        float acc = linb[tid];
        const float4* w = (const float4*)(linW + (size_t)tid*2*HH);
        const float4* h = (const float4*)hcat;
        #pragma unroll 8
        for (int k = 0; k < (2*HH)/4; k++){
            float4 ww = w[k]; float4 hh = h[k];
            acc += ww.x*hh.x + ww.y*hh.y + ww.z*hh.z + ww.w*hh.w;
        }
        logit = acc * (1.0f/TAUF);
        v = logit;
    }
    red[tid] = v; __syncthreads();
    for (int s = 256; s > 0; s >>= 1){ if (tid < s) red[tid] = fmaxf(red[tid], red[tid+s]); __syncthreads(); }
    float m = red[0]; __syncthreads();
    float e = (tid < NRELS) ? expf(logit - m) : 0.0f;
    red[tid] = e; __syncthreads();
    for (int s = 256; s > 0; s >>= 1){ if (tid < s) red[tid] += red[tid+s]; __syncthreads(); }
    float sum = red[0];
    if (tid < NRELS)
        g_W[(((size_t)t*Bz + b)*Lc + l)*NRELS + tid] = e / sum;
}

// ---------------- 3) CSR build ----------------
__global__ void zero_counts_kernel(){
    int i = blockIdx.x*blockDim.x + threadIdx.x;
    if (i <= ENT){ g_offf[i] = 0; g_offb[i] = 0; }
}

__global__ void hist_kernel(const int* __restrict__ e2triple){
    int n = blockIdx.x*blockDim.x + threadIdx.x;
    if (n < NTR){
        atomicAdd(&g_offf[e2triple[n]], 1);            // row 0: heads
        atomicAdd(&g_offb[e2triple[2*NTR + n]], 1);    // row 2: tails2
    }
}

__global__ void scan_kernel(){
    int* cnt = blockIdx.x ? g_offb : g_offf;
    int* cur = blockIdx.x ? g_curb : g_curf;
    __shared__ int part[1024];
    const int CH = (ENT + 1023)/1024;
    int tid = threadIdx.x;
    int beg = tid*CH;
    int end = min(beg + CH, ENT);
    int s = 0;
    for (int e = beg; e < end; e++) s += cnt[e];
    part[tid] = s; __syncthreads();
    if (tid == 0){
        int run = 0;
        for (int i = 0; i < 1024; i++){ int t = part[i]; part[i] = run; run += t; }
    }
    __syncthreads();
    int run = part[tid];
    for (int e = beg; e < end; e++){ int t = cnt[e]; cnt[e] = run; cur[e] = run; run += t; }
    if (tid == 1023) cnt[ENT] = run;
}

__global__ void fill_kernel(const int* __restrict__ e2triple, const int* __restrict__ triple2e,
                            const int* __restrict__ r2triple){
    int n = blockIdx.x*blockDim.x + threadIdx.x;
    if (n < NTR){
        int h  = e2triple[n];
        int t2 = e2triple[2*NTR + n];
        int tl = triple2e[NTR + n];   // row 1: tails
        int r  = r2triple[n];
        int p = atomicAdd(&g_curf[h], 1);
        g_payf[p] = (unsigned)tl | ((unsigned)r << 16);   // entity fits 16b (E<65536), rel fits 16b
        int q = atomicAdd(&g_curb[t2], 1);
        g_payb[q] = (unsigned)h  | ((unsigned)r << 16);
    }
}

// ---------------- 4) hops ----------------
__global__ void zero_snext_kernel(){
    int i = blockIdx.x*blockDim.x + threadIdx.x;
    if (i < Bz*Lc*ENT) g_snext[i] = 0.0f;
}

// hop 0: input is one-hot at input_x[b] for every channel l
__global__ void hop0_kernel(const int* __restrict__ input_x){
    int b = blockIdx.x / Lc, l = blockIdx.x % Lc;
    int e0 = input_x[b];
    const float* w = g_W + (((size_t)0*Bz + b)*Lc + l)*NRELS;
    float* out = g_snext + (size_t)(b*Lc + l)*ENT;
    int tid = threadIdx.x;
    if (tid == 0) atomicAdd(&out[e0], w[NRELS-1]);        // identity relation
    int s0 = g_offf[e0], s1 = g_offf[e0+1];
    for (int i = s0 + tid; i < s1; i += blockDim.x){
        unsigned p = g_payf[i];
        atomicAdd(&out[p & 0xFFFFu], w[p >> 16]);
    }
    s0 = g_offb[e0]; s1 = g_offb[e0+1];
    for (int i = s0 + tid; i < s1; i += blockDim.x){
        unsigned p = g_payb[i];
        atomicAdd(&out[p & 0xFFFFu], w[(p >> 16) + RR]);
    }
}

__global__ void normalize_kernel(){
    int slice = blockIdx.x;                 // 24 blocks x 1024 threads
    size_t base = (size_t)slice*ENT;
    __shared__ float red[1024];
    int tid = threadIdx.x;
    float s = 0.0f;
    for (int e = tid; e < ENT; e += 1024) s += g_snext[base+e];
    red[tid] = s; __syncthreads();
    for (int st = 512; st > 0; st >>= 1){ if (tid < st) red[tid] += red[tid+st]; __syncthreads(); }
    float inv = 1.0f / fmaxf(red[0], 1e-7f);
    for (int e = tid; e < ENT; e += 1024) g_scur[base+e] = g_snext[base+e]*inv;
}

// exact k-th largest per slice via 4-pass byte radix select (values are nonnegative floats)
__global__ void topk_kernel(){
    int slice = blockIdx.x;
    size_t base = (size_t)slice*ENT;
    __shared__ unsigned hist[256];
    __shared__ unsigned s_prefix;
    __shared__ int s_krem;
    int tid = threadIdx.x;
    if (tid == 0){ s_prefix = 0; s_krem = TOPKN; }
    __syncthreads();
    for (int pass = 0; pass < 4; pass++){
        int shift = 24 - 8*pass;
        if (tid < 256) hist[tid] = 0;
        __syncthreads();
        unsigned pref = s_prefix;
        for (int e = tid; e < ENT; e += blockDim.x){
            unsigned u = __float_as_uint(g_scur[base+e]);
            if (pass == 0 || (u >> (shift+8)) == pref)
                atomicAdd(&hist[(u >> shift) & 0xFFu], 1u);
        }
        __syncthreads();
        if (tid == 0){
            int c = 0; int bin = 255;
            for (; bin > 0; bin--){
                if (c + (int)hist[bin] >= s_krem) break;
                c += (int)hist[bin];
            }
            s_krem -= c;
            s_prefix = (s_prefix << 8) | (unsigned)bin;
        }
        __syncthreads();
    }
    if (tid == 0) g_th[slice] = __uint_as_float(s_prefix);
}

// sparse propagate: one thread per (slice, entity); only top-k survivors expand
__global__ void propagate_kernel(int t){
    int slice = blockIdx.y;
    int b = slice / Lc, l = slice % Lc;
    __shared__ float wsh[NRELS];
    int tid = threadIdx.x;
    const float* w = g_W + (((size_t)t*Bz + b)*Lc + l)*NRELS;
    for (int i = tid; i < NRELS; i += blockDim.x) wsh[i] = w[i];
    __syncthreads();
    int e = blockIdx.x*blockDim.x + tid;
    if (e >= ENT) return;
    size_t base = (size_t)slice*ENT;
    float v = g_scur[base+e];
    if (!(v > 0.0f && v >= g_th[slice])) return;
    float* out = g_snext + base;
    atomicAdd(&out[e], v*wsh[NRELS-1]);                       // identity on pruned value
    int s0 = g_offf[e], s1 = g_offf[e+1];
    for (int i = s0; i < s1; i++){
        unsigned p = g_payf[i];
        atomicAdd(&out[p & 0xFFFFu], v*wsh[p >> 16]);
    }
    s0 = g_offb[e]; s1 = g_offb[e+1];
    for (int i = s0; i < s1; i++){
        unsigned p = g_payb[i];
        atomicAdd(&out[p & 0xFFFFu], v*wsh[(p >> 16) + RR]);
    }
}

__global__ void final_kernel(float* __restrict__ out){
    int i = blockIdx.x*blockDim.x + threadIdx.x;
    if (i < Bz*ENT){
        int b = i / ENT, e = i % ENT;
        float s = 0.0f;
        for (int l = 0; l < Lc; l++) s += g_scur[((size_t)(b*Lc + l))*ENT + e];
        out[i] = s;
    }
}

// ---------------- launcher (graph-capturable: kernels only) ----------------
extern "C" void kernel_launch(void* const* d_in, const int* in_sizes, int n_in,
                              void* d_out, int out_size)
{
    const int*   input_x  = (const int*)  d_in[0];
    const int*   input_r  = (const int*)  d_in[1];
    const int*   e2triple = (const int*)  d_in[2];
    const int*   triple2e = (const int*)  d_in[3];
    const int*   r2triple = (const int*)  d_in[4];
    const float* emb      = (const float*)d_in[5];
    const float* Wih_f    = (const float*)d_in[6];
    const float* Whh_f    = (const float*)d_in[7];
    const float* bih_f    = (const float*)d_in[8];
    const float* bhh_f    = (const float*)d_in[9];
    const float* Wih_b    = (const float*)d_in[10];
    const float* Whh_b    = (const float*)d_in[11];
    const float* bih_b    = (const float*)d_in[12];
    const float* bhh_b    = (const float*)d_in[13];
    const float* linW     = (const float*)d_in[14];
    const float* linb     = (const float*)d_in[15];
    float* out = (float*)d_out;

    // rule scorer (tiny)
    lstm_kernel<<<Lc*2*Bz, 1024>>>(input_r, emb, Wih_f, Whh_f, bih_f, bhh_f,
                                   Wih_b, Whh_b, bih_b, bhh_b);
    wsoft_kernel<<<Bz*Tt*Lc, 512>>>(linW, linb);

    // CSR build (rebuilt every call — no caching)
    zero_counts_kernel<<<(ENT+1+255)/256, 256>>>();
    hist_kernel<<<(NTR+255)/256, 256>>>(e2triple);
    scan_kernel<<<2, 1024>>>();
    fill_kernel<<<(NTR+255)/256, 256>>>(e2triple, triple2e, r2triple);

    // hop 0 (one-hot input)
    zero_snext_kernel<<<(Bz*Lc*ENT+255)/256, 256>>>();
    hop0_kernel<<<Bz*Lc, 256>>>(input_x);
    normalize_kernel<<<Bz*Lc, 1024>>>();

    // hops 1..T-1 (top-k sparse)
    for (int t = 1; t < Tt; t++){
        topk_kernel<<<Bz*Lc, 1024>>>();
        zero_snext_kernel<<<(Bz*Lc*ENT+255)/256, 256>>>();
        propagate_kernel<<<dim3((ENT+255)/256, Bz*Lc), 256>>>(t);
        normalize_kernel<<<Bz*Lc, 1024>>>();
    }

    final_kernel<<<(Bz*ENT+255)/256, 256>>>(out);
}